// round 2
// baseline (speedup 1.0000x reference)
#include <cuda_runtime.h>
#include <cuda_bf16.h>
#include <math.h>

#define KT  23
#define TSTART 21
#define TSTOP  22
#define NEGV (-10000.0f)
#define TN  8192
#define EE  50
#define HHD 128
#define GG  512   // 4*HHD

// ---------------- device scratch (static, no allocations) ----------------
__device__ float d_pre[2u * TN * GG];          // 32 MB  pre-gates per dir/time
__device__ float d_houtg[2u * TN * HHD];       // 8 MB   hidden states per dir/time
__device__ float d_feats[TN * KT];             // 753 KB
__device__ ulonglong2 d_wt[2 * 8 * GG];        // transposed streamed weight cols 96..127
__device__ float d_score_g;
__device__ int   d_tags_g[TN];

// ---------------- helpers ----------------
__device__ __forceinline__ void fma2(unsigned long long& d,
                                     unsigned long long a,
                                     unsigned long long b) {
    asm("fma.rn.f32x2 %0, %1, %2, %0;" : "+l"(d) : "l"(a), "l"(b));
}
__device__ __forceinline__ float ull_lo(unsigned long long v) {
    return __uint_as_float((unsigned)(v & 0xffffffffull));
}
__device__ __forceinline__ float ull_hi(unsigned long long v) {
    return __uint_as_float((unsigned)(v >> 32));
}
__device__ __forceinline__ float sigmoid_f(float x) {
    return __fdividef(1.0f, 1.0f + __expf(-x));
}
__device__ __forceinline__ float tanh_f(float x) {
    float xc = fminf(fmaxf(x, -12.0f), 12.0f);
    float e = __expf(2.0f * xc);
    return __fdividef(e - 1.0f, e + 1.0f);
}

// ---------------- kernel 0: transpose streamed weight slice ----------------
// d_wt[(dir*8 + j)*512 + r] = Whh_dir[r][96+4j .. 96+4j+3]
__global__ void prep_wt_kernel(const float* __restrict__ Whh_f,
                               const float* __restrict__ Whh_b) {
    int i = blockIdx.x * blockDim.x + threadIdx.x;
    if (i >= 2 * 8 * GG) return;
    int r = i & 511;
    int j = (i >> 9) & 7;
    int d = i >> 12;
    const float* W = d ? Whh_b : Whh_f;
    d_wt[i - 0] = *(const ulonglong2*)(W + r * HHD + 96 + 4 * j);
    // note: flat index i == (d*8 + j)*512 + r by construction
}

// ---------------- kernel 1: embedding + input-gate precompute ----------------
// d_pre[(dir*TN + t)*512 + r] = Wih_dir[r,:] @ x_t + bih[r] + bhh[r]
__global__ void pre_kernel(const int* __restrict__ sentence,
                           const float* __restrict__ embed,
                           const float* __restrict__ Wih_f,
                           const float* __restrict__ bih_f,
                           const float* __restrict__ bhh_f,
                           const float* __restrict__ Wih_b,
                           const float* __restrict__ bih_b,
                           const float* __restrict__ bhh_b) {
    const int TT = 64;
    __shared__ float sx[TT * EE];
    int t0 = blockIdx.x * TT;
    int tid = threadIdx.x;   // 512
    for (int idx = tid; idx < TT * EE; idx += 512) {
        int tl = idx / EE, e = idx - tl * EE;
        sx[idx] = embed[(size_t)sentence[t0 + tl] * EE + e];
    }
    __syncthreads();
    int r = tid;
    for (int d = 0; d < 2; d++) {
        const float* Wih = d ? Wih_b : Wih_f;
        const float* bi  = d ? bih_b : bih_f;
        const float* bh  = d ? bhh_b : bhh_f;
        float w[EE];
#pragma unroll
        for (int e = 0; e < EE; e++) w[e] = Wih[r * EE + e];
        float bs = bi[r] + bh[r];
        for (int tl = 0; tl < TT; tl++) {
            float acc = bs;
#pragma unroll
            for (int e = 0; e < EE; e++) acc += w[e] * sx[tl * EE + e];
            d_pre[((size_t)d * TN + (t0 + tl)) * GG + r] = acc;
        }
    }
}

// ---------------- kernel 2: the sequential LSTM (one CTA per direction) ----
__global__ __launch_bounds__(512, 1)
void lstm_kernel(const float* __restrict__ Whh_f,
                 const float* __restrict__ Whh_b,
                 const float* __restrict__ h0,
                 const float* __restrict__ c0) {
    int dir = blockIdx.x;
    int r = threadIdx.x;                 // row 0..511
    const float* Whh = dir ? Whh_b : Whh_f;

    // register-resident weight columns 0..95 (48 packed pairs)
    unsigned long long wr[48];
    const unsigned long long* wrow = (const unsigned long long*)(Whh + r * HHD);
#pragma unroll
    for (int j = 0; j < 48; j++) wr[j] = wrow[j];

    __shared__ float s_h[HHD];
    __shared__ float s_gate[GG];

    float c = 0.0f;
    if (r < HHD) {
        s_h[r] = h0[dir * HHD + r];
        c      = c0[dir * HHD + r];
    }
    const float* pre = d_pre + (size_t)dir * TN * GG;
    float* hout = d_houtg + (size_t)dir * TN * HHD;
    const ulonglong2* wt = d_wt + dir * 8 * GG;
    __syncthreads();

    for (int s = 0; s < TN; s++) {
        int t = dir ? (TN - 1 - s) : s;
        float pv = pre[(size_t)t * GG + r];
        unsigned long long acc = 0ull, acc2 = 0ull;
        const ulonglong2* h2 = (const ulonglong2*)s_h;
#pragma unroll
        for (int j = 0; j < 24; j++) {
            ulonglong2 hv = h2[j];
            fma2(acc,  wr[2 * j],     hv.x);
            fma2(acc2, wr[2 * j + 1], hv.y);
        }
#pragma unroll
        for (int j = 0; j < 8; j++) {
            ulonglong2 hv = h2[24 + j];
            ulonglong2 wv = wt[j * GG + r];
            fma2(acc,  wv.x, hv.x);
            fma2(acc2, wv.y, hv.y);
        }
        float partial = (ull_lo(acc) + ull_hi(acc)) + (ull_lo(acc2) + ull_hi(acc2)) + pv;
        s_gate[r] = partial;
        __syncthreads();
        if (r < HHD) {
            float gi = s_gate[r];
            float gf = s_gate[HHD + r];
            float gg = s_gate[2 * HHD + r];
            float go = s_gate[3 * HHD + r];
            float iv = sigmoid_f(gi);
            float fv = sigmoid_f(gf);
            float gv = tanh_f(gg);
            float ov = sigmoid_f(go);
            c = fv * c + iv * gv;
            float hn = ov * tanh_f(c);
            s_h[r] = hn;
            hout[(size_t)t * HHD + r] = hn;
        }
        __syncthreads();
    }
}

// ---------------- kernel 3: output projection ----------------
__global__ void feats_kernel(const float* __restrict__ W_out,
                             const float* __restrict__ b_out) {
    int t = blockIdx.x;
    int tid = threadIdx.x;   // 256
    __shared__ float s_hc[256];
    s_hc[tid] = (tid < HHD) ? d_houtg[(size_t)t * HHD + tid]
                            : d_houtg[(size_t)TN * HHD + (size_t)t * HHD + (tid - HHD)];
    __syncthreads();
    int w = tid >> 5, l = tid & 31;
    for (int k = w; k < KT; k += 8) {
        float acc = 0.0f;
#pragma unroll
        for (int j = l; j < 256; j += 32) acc += W_out[k * 256 + j] * s_hc[j];
#pragma unroll
        for (int off = 16; off; off >>= 1) acc += __shfl_down_sync(0xffffffffu, acc, off);
        if (l == 0) d_feats[t * KT + k] = acc + b_out[k];
    }
}

// ---------------- kernel 4: Viterbi (single warp) ----------------
__global__ void viterbi_kernel(const float* __restrict__ transitions) {
    extern __shared__ unsigned char sbp[];   // TN * KT backpointers
    int lane = threadIdx.x;
    bool act = lane < KT;
    float tr[KT];
#pragma unroll
    for (int p = 0; p < KT; p++) {
        float v = NEGV;
        if (act) {
            v = transitions[lane * KT + p];
            if (lane == TSTART) v = NEGV;   // nothing transitions into START
            if (p == TSTOP)     v = NEGV;   // nothing transitions out of STOP
        }
        tr[p] = v;
    }
    float trS = act ? ((lane == TSTOP) ? NEGV : transitions[TSTOP * KT + lane]) : NEGV;
    float fv = (lane == TSTART) ? 0.0f : NEGV;

    float f0 = act ? d_feats[0 * KT + lane] : 0.0f;
    float f1 = act ? d_feats[1 * KT + lane] : 0.0f;
    float f2 = act ? d_feats[2 * KT + lane] : 0.0f;

    for (int t = 0; t < TN; t++) {
        float fn = 0.0f;
        if (act && t + 3 < TN) fn = d_feats[(t + 3) * KT + lane];
        float best = __shfl_sync(0xffffffffu, fv, 0) + tr[0];
        int bp = 0;
#pragma unroll
        for (int p = 1; p < KT; p++) {
            float v = __shfl_sync(0xffffffffu, fv, p) + tr[p];
            if (v > best) { best = v; bp = p; }   // first-max semantics
        }
        fv = best + f0;
        if (act) sbp[t * KT + lane] = (unsigned char)bp;
        f0 = f1; f1 = f2; f2 = fn;
    }

    float term = act ? (fv + trS) : NEGV;
    int idx = lane;
#pragma unroll
    for (int off = 16; off; off >>= 1) {
        float ov = __shfl_down_sync(0xffffffffu, term, off);
        int   oi = __shfl_down_sync(0xffffffffu, idx,  off);
        if (ov > term || (ov == term && oi < idx)) { term = ov; idx = oi; }
    }
    __syncwarp();
    if (lane == 0) {
        d_score_g = term;
        int tag = idx;
        d_tags_g[TN - 1] = tag;
        for (int t = TN - 1; t > 0; t--) {
            tag = sbp[t * KT + tag];
            d_tags_g[t - 1] = tag;
        }
    }
}

// ---------------- kernel 5: write output ----------------
__global__ void epilogue_kernel(float* __restrict__ out, int n) {
    int i = blockIdx.x * blockDim.x + threadIdx.x;
    if (i >= n) return;
    float v;
    if (n == TN) {
        v = (float)d_tags_g[i];
    } else if (n == 1) {
        v = d_score_g;
    } else {
        v = (i == 0) ? d_score_g
                     : ((i - 1 < TN) ? (float)d_tags_g[i - 1] : 0.0f);
    }
    out[i] = v;
}

// ---------------- launch ----------------
extern "C" void kernel_launch(void* const* d_in, const int* in_sizes, int n_in,
                              void* d_out, int out_size) {
    const int*   sentence = (const int*)  d_in[0];
    const float* embed    = (const float*)d_in[1];
    const float* Wih_f    = (const float*)d_in[2];
    const float* Whh_f    = (const float*)d_in[3];
    const float* bih_f    = (const float*)d_in[4];
    const float* bhh_f    = (const float*)d_in[5];
    const float* Wih_b    = (const float*)d_in[6];
    const float* Whh_b    = (const float*)d_in[7];
    const float* bih_b    = (const float*)d_in[8];
    const float* bhh_b    = (const float*)d_in[9];
    const float* W_out    = (const float*)d_in[10];
    const float* b_out    = (const float*)d_in[11];
    const float* trans    = (const float*)d_in[12];
    const float* h0       = (const float*)d_in[13];
    const float* c0       = (const float*)d_in[14];

    prep_wt_kernel<<<16, 512>>>(Whh_f, Whh_b);
    pre_kernel<<<TN / 64, 512>>>(sentence, embed, Wih_f, bih_f, bhh_f,
                                 Wih_b, bih_b, bhh_b);
    lstm_kernel<<<2, 512>>>(Whh_f, Whh_b, h0, c0);
    feats_kernel<<<TN, 256>>>(W_out, b_out);

    int vit_smem = TN * KT + 64;   // ~188.5 KB
    cudaFuncSetAttribute(viterbi_kernel,
                         cudaFuncAttributeMaxDynamicSharedMemorySize, vit_smem);
    viterbi_kernel<<<1, 32, vit_smem>>>(trans);

    int n = out_size;
    epilogue_kernel<<<(n + 255) / 256, 256>>>((float*)d_out, n);
}

// round 3
// speedup vs baseline: 1.1483x; 1.1483x over previous
#include <cuda_runtime.h>
#include <cuda_bf16.h>
#include <math.h>

#define KT  23
#define TSTART 21
#define TSTOP  22
#define NEGV (-10000.0f)
#define TN  8192
#define EE  50
#define HHD 128
#define GG  512   // 4*HHD

// ---------------- device scratch (static, no allocations) ----------------
__device__ float d_pre[2u * TN * GG];          // 32 MB  pre-gates per dir/time
__device__ float d_houtg[2u * TN * HHD];       // 8 MB   hidden states per dir/time
__device__ float d_feats[TN * KT];             // 753 KB
__device__ float d_score_g;
__device__ int   d_tags_g[TN];

// ---------------- helpers ----------------
__device__ __forceinline__ void fma2(unsigned long long& d,
                                     unsigned long long a,
                                     unsigned long long b) {
    asm("fma.rn.f32x2 %0, %1, %2, %0;" : "+l"(d) : "l"(a), "l"(b));
}
__device__ __forceinline__ float ull_lo(unsigned long long v) {
    return __uint_as_float((unsigned)(v & 0xffffffffull));
}
__device__ __forceinline__ float ull_hi(unsigned long long v) {
    return __uint_as_float((unsigned)(v >> 32));
}
__device__ __forceinline__ float sigmoid_f(float x) {
    return __fdividef(1.0f, 1.0f + __expf(-x));
}
__device__ __forceinline__ float tanh_f(float x) {
    float xc = fminf(fmaxf(x, -12.0f), 12.0f);
    float e = __expf(2.0f * xc);
    return __fdividef(e - 1.0f, e + 1.0f);
}
__device__ __forceinline__ unsigned smem_u32(const void* p) {
    unsigned a;
    asm("{ .reg .u64 t; cvta.to.shared.u64 t, %1; cvt.u32.u64 %0, t; }"
        : "=r"(a) : "l"(p));
    return a;
}
__device__ __forceinline__ void st_remote_f32(unsigned local_addr, unsigned peer_rank, float v) {
    asm volatile(
        "{\n\t.reg .b32 ra;\n\t"
        "mapa.shared::cluster.u32 ra, %0, %1;\n\t"
        "st.shared::cluster.f32 [ra], %2;\n\t}"
        :: "r"(local_addr), "r"(peer_rank), "f"(v) : "memory");
}
__device__ __forceinline__ void arrive_remote(unsigned local_mbar, unsigned peer_rank) {
    asm volatile(
        "{\n\t.reg .b32 ra;\n\t"
        "mapa.shared::cluster.u32 ra, %0, %1;\n\t"
        "mbarrier.arrive.release.cluster.shared::cluster.b64 _, [ra];\n\t}"
        :: "r"(local_mbar), "r"(peer_rank) : "memory");
}
__device__ __forceinline__ void mbar_wait_parity_cluster(unsigned mbar, unsigned parity) {
    asm volatile(
        "{\n\t.reg .pred P;\n\t"
        "W_%=:\n\t"
        "mbarrier.try_wait.parity.acquire.cluster.shared::cta.b64 P, [%0], %1, 0x989680;\n\t"
        "@P bra.uni D_%=;\n\t"
        "bra.uni W_%=;\n\t"
        "D_%=:\n\t}"
        :: "r"(mbar), "r"(parity) : "memory");
}

// ---------------- kernel 1: embedding + input-gate precompute ----------------
// d_pre[(dir*TN + t)*512 + r] = Wih_dir[r,:] @ x_t + bih[r] + bhh[r]
__global__ void pre_kernel(const int* __restrict__ sentence,
                           const float* __restrict__ embed,
                           const float* __restrict__ Wih_f,
                           const float* __restrict__ bih_f,
                           const float* __restrict__ bhh_f,
                           const float* __restrict__ Wih_b,
                           const float* __restrict__ bih_b,
                           const float* __restrict__ bhh_b) {
    const int TT = 64;
    __shared__ float sx[TT * EE];
    int t0 = blockIdx.x * TT;
    int tid = threadIdx.x;   // 512
    for (int idx = tid; idx < TT * EE; idx += 512) {
        int tl = idx / EE, e = idx - tl * EE;
        sx[idx] = embed[(size_t)sentence[t0 + tl] * EE + e];
    }
    __syncthreads();
    int r = tid;
    for (int d = 0; d < 2; d++) {
        const float* Wih = d ? Wih_b : Wih_f;
        const float* bi  = d ? bih_b : bih_f;
        const float* bh  = d ? bhh_b : bhh_f;
        float w[EE];
#pragma unroll
        for (int e = 0; e < EE; e++) w[e] = Wih[r * EE + e];
        float bs = bi[r] + bh[r];
        for (int tl = 0; tl < TT; tl++) {
            float acc = bs;
#pragma unroll
            for (int e = 0; e < EE; e++) acc += w[e] * sx[tl * EE + e];
            d_pre[((size_t)d * TN + (t0 + tl)) * GG + r] = acc;
        }
    }
}

// ---------------- dummy (positions ncu capture window on lstm) -------------
__global__ void dummy_kernel() {}

// ---------------- kernel 2: sequential LSTM (2-CTA cluster per direction) --
// grid = 4 CTAs, cluster dims (2,1,1). dir = blockIdx.x>>1, rank q = ctarank.
// CTA q owns hidden dims [64q, 64q+64): gate rows { g*128 + 64q + j }.
// Thread rl in [0,256): g = rl>>6, j = rl&63, global row R = g*128 + 64q + j.
// All 128 weight columns register-resident (64 ull = 128 regs, cap 255).
__global__ void __cluster_dims__(2, 1, 1) __launch_bounds__(256, 1)
lstm_kernel(const float* __restrict__ Whh_f,
            const float* __restrict__ Whh_b,
            const float* __restrict__ h0,
            const float* __restrict__ c0) {
    __shared__ float s_h[2][HHD];
    __shared__ float s_gate[256];
    __shared__ __align__(8) unsigned long long s_mbar;

    const int dir = blockIdx.x >> 1;
    unsigned q;
    asm("mov.u32 %0, %%cluster_ctarank;" : "=r"(q));
    const unsigned peer = q ^ 1u;

    const int rl = threadIdx.x;          // 0..255
    const int g  = rl >> 6;
    const int j  = rl & 63;
    const int R  = g * HHD + (int)(64u * q) + j;   // global gate row

    const float* Whh = dir ? Whh_b : Whh_f;

    // register-resident full weight row (128 floats = 64 ull)
    unsigned long long wr[64];
    const unsigned long long* wrow = (const unsigned long long*)(Whh + (size_t)R * HHD);
#pragma unroll
    for (int k = 0; k < 64; k++) wr[k] = wrow[k];

    // init h buffer 0 and c
    if (rl < HHD) s_h[0][rl] = h0[dir * HHD + rl];
    float c = 0.0f;
    if (rl < 64) c = c0[dir * HHD + 64u * q + j];

    unsigned mbar_addr = smem_u32(&s_mbar);
    if (rl == 0) {
        asm volatile("mbarrier.init.shared.b64 [%0], 64;" :: "r"(mbar_addr) : "memory");
    }
    __syncthreads();
    // both CTAs' mbarriers + h buffers ready before any remote traffic
    asm volatile("barrier.cluster.arrive.aligned;" ::: "memory");
    asm volatile("barrier.cluster.wait.aligned;" ::: "memory");

    const float* pre = d_pre + (size_t)dir * TN * GG;
    float* hout = d_houtg + (size_t)dir * TN * HHD;

    unsigned h_next_addr0 = smem_u32(&s_h[0][64u * q + j]);   // this thread's slot, buffer 0
    unsigned h_next_addr1 = smem_u32(&s_h[1][64u * q + j]);   // buffer 1

    for (int s = 0; s < TN; s++) {
        const int cb = s & 1;
        const int t = dir ? (TN - 1 - s) : s;
        float pv = pre[(size_t)t * GG + R];

        unsigned long long a0 = 0ull, a1 = 0ull, a2 = 0ull, a3 = 0ull;
        const ulonglong2* h2 = (const ulonglong2*)s_h[cb];
#pragma unroll
        for (int k = 0; k < 16; k++) {
            ulonglong2 hva = h2[2 * k];
            ulonglong2 hvb = h2[2 * k + 1];
            fma2(a0, wr[4 * k + 0], hva.x);
            fma2(a1, wr[4 * k + 1], hva.y);
            fma2(a2, wr[4 * k + 2], hvb.x);
            fma2(a3, wr[4 * k + 3], hvb.y);
        }
        float partial = ((ull_lo(a0) + ull_hi(a0)) + (ull_lo(a1) + ull_hi(a1)))
                      + ((ull_lo(a2) + ull_hi(a2)) + (ull_lo(a3) + ull_hi(a3))) + pv;
        s_gate[rl] = partial;
        __syncthreads();

        if (rl < 64) {
            float gi = s_gate[j];
            float gf = s_gate[64 + j];
            float gg = s_gate[128 + j];
            float go = s_gate[192 + j];
            float iv = sigmoid_f(gi);
            float fv = sigmoid_f(gf);
            float gv = tanh_f(gg);
            float ov = sigmoid_f(go);
            c = fv * c + iv * gv;
            float hn = ov * tanh_f(c);
            // local write into next buffer
            s_h[cb ^ 1][64u * q + j] = hn;
            // remote write into peer's next buffer + release-arrive on peer's mbar
            st_remote_f32(cb ? h_next_addr0 : h_next_addr1, peer, hn);
            arrive_remote(mbar_addr, peer);
            hout[(size_t)t * HHD + 64u * q + j] = hn;
        }
        __syncthreads();                       // local h writes + s_gate reuse
        mbar_wait_parity_cluster(mbar_addr, (unsigned)(s & 1));   // remote h arrived
    }
}

// ---------------- kernel 3: output projection ----------------
__global__ void feats_kernel(const float* __restrict__ W_out,
                             const float* __restrict__ b_out) {
    int t = blockIdx.x;
    int tid = threadIdx.x;   // 256
    __shared__ float s_hc[256];
    s_hc[tid] = (tid < HHD) ? d_houtg[(size_t)t * HHD + tid]
                            : d_houtg[(size_t)TN * HHD + (size_t)t * HHD + (tid - HHD)];
    __syncthreads();
    int w = tid >> 5, l = tid & 31;
    for (int k = w; k < KT; k += 8) {
        float acc = 0.0f;
#pragma unroll
        for (int jj = l; jj < 256; jj += 32) acc += W_out[k * 256 + jj] * s_hc[jj];
#pragma unroll
        for (int off = 16; off; off >>= 1) acc += __shfl_down_sync(0xffffffffu, acc, off);
        if (l == 0) d_feats[t * KT + k] = acc + b_out[k];
    }
}

// ---------------- kernel 4: Viterbi (single warp) ----------------
__global__ void viterbi_kernel(const float* __restrict__ transitions) {
    extern __shared__ unsigned char sbp[];   // TN * KT backpointers
    int lane = threadIdx.x;
    bool act = lane < KT;
    float tr[KT];
#pragma unroll
    for (int p = 0; p < KT; p++) {
        float v = NEGV;
        if (act) {
            v = transitions[lane * KT + p];
            if (lane == TSTART) v = NEGV;   // nothing transitions into START
            if (p == TSTOP)     v = NEGV;   // nothing transitions out of STOP
        }
        tr[p] = v;
    }
    float trS = act ? ((lane == TSTOP) ? NEGV : transitions[TSTOP * KT + lane]) : NEGV;
    float fv = (lane == TSTART) ? 0.0f : NEGV;

    float f0 = act ? d_feats[0 * KT + lane] : 0.0f;
    float f1 = act ? d_feats[1 * KT + lane] : 0.0f;
    float f2 = act ? d_feats[2 * KT + lane] : 0.0f;

    for (int t = 0; t < TN; t++) {
        float fn = 0.0f;
        if (act && t + 3 < TN) fn = d_feats[(t + 3) * KT + lane];
        float best = __shfl_sync(0xffffffffu, fv, 0) + tr[0];
        int bp = 0;
#pragma unroll
        for (int p = 1; p < KT; p++) {
            float v = __shfl_sync(0xffffffffu, fv, p) + tr[p];
            if (v > best) { best = v; bp = p; }   // first-max semantics
        }
        fv = best + f0;
        if (act) sbp[t * KT + lane] = (unsigned char)bp;
        f0 = f1; f1 = f2; f2 = fn;
    }

    float term = act ? (fv + trS) : NEGV;
    int idx = lane;
#pragma unroll
    for (int off = 16; off; off >>= 1) {
        float ov = __shfl_down_sync(0xffffffffu, term, off);
        int   oi = __shfl_down_sync(0xffffffffu, idx,  off);
        if (ov > term || (ov == term && oi < idx)) { term = ov; idx = oi; }
    }
    __syncwarp();
    if (lane == 0) {
        d_score_g = term;
        int tag = idx;
        d_tags_g[TN - 1] = tag;
        for (int t = TN - 1; t > 0; t--) {
            tag = sbp[t * KT + tag];
            d_tags_g[t - 1] = tag;
        }
    }
}

// ---------------- kernel 5: write output ----------------
__global__ void epilogue_kernel(float* __restrict__ out, int n) {
    int i = blockIdx.x * blockDim.x + threadIdx.x;
    if (i >= n) return;
    float v;
    if (n == TN) {
        v = (float)d_tags_g[i];
    } else if (n == 1) {
        v = d_score_g;
    } else {
        v = (i == 0) ? d_score_g
                     : ((i - 1 < TN) ? (float)d_tags_g[i - 1] : 0.0f);
    }
    out[i] = v;
}

// ---------------- launch ----------------
extern "C" void kernel_launch(void* const* d_in, const int* in_sizes, int n_in,
                              void* d_out, int out_size) {
    const int*   sentence = (const int*)  d_in[0];
    const float* embed    = (const float*)d_in[1];
    const float* Wih_f    = (const float*)d_in[2];
    const float* Whh_f    = (const float*)d_in[3];
    const float* bih_f    = (const float*)d_in[4];
    const float* bhh_f    = (const float*)d_in[5];
    const float* Wih_b    = (const float*)d_in[6];
    const float* Whh_b    = (const float*)d_in[7];
    const float* bih_b    = (const float*)d_in[8];
    const float* bhh_b    = (const float*)d_in[9];
    const float* W_out    = (const float*)d_in[10];
    const float* b_out    = (const float*)d_in[11];
    const float* trans    = (const float*)d_in[12];
    const float* h0       = (const float*)d_in[13];
    const float* c0       = (const float*)d_in[14];

    pre_kernel<<<TN / 64, 512>>>(sentence, embed, Wih_f, bih_f, bhh_f,
                                 Wih_b, bih_b, bhh_b);                    // launch 1
    dummy_kernel<<<1, 32>>>();                                            // launch 2
    dummy_kernel<<<1, 32>>>();                                            // launch 3
    lstm_kernel<<<4, 256>>>(Whh_f, Whh_b, h0, c0);                        // launch 4 (ncu window)
    feats_kernel<<<TN, 256>>>(W_out, b_out);                              // launch 5

    int vit_smem = TN * KT + 64;   // ~188.5 KB
    cudaFuncSetAttribute(viterbi_kernel,
                         cudaFuncAttributeMaxDynamicSharedMemorySize, vit_smem);
    viterbi_kernel<<<1, 32, vit_smem>>>(trans);                           // launch 6

    int n = out_size;
    epilogue_kernel<<<(n + 255) / 256, 256>>>((float*)d_out, n);          // launch 7
}

// round 7
// speedup vs baseline: 1.1730x; 1.0215x over previous
#include <cuda_runtime.h>
#include <cuda_bf16.h>
#include <math.h>

#define KT  23
#define TSTART 21
#define TSTOP  22
#define NEGV (-10000.0f)
#define TN  8192
#define EE  50
#define HHD 128
#define GG  512   // 4*HHD

// ---------------- device scratch (static, no allocations) ----------------
__device__ float d_pre[2u * TN * GG];          // 32 MB  pre-gates per dir/time
__device__ float d_houtg[2u * TN * HHD];       // 8 MB   hidden states per dir/time
__device__ float d_feats[TN * KT];             // 753 KB
__device__ float d_score_g;
__device__ int   d_tags_g[TN];

// ---------------- helpers ----------------
__device__ __forceinline__ void fma2(unsigned long long& d,
                                     unsigned long long a,
                                     unsigned long long b) {
    asm("fma.rn.f32x2 %0, %1, %2, %0;" : "+l"(d) : "l"(a), "l"(b));
}
__device__ __forceinline__ float ull_lo(unsigned long long v) {
    return __uint_as_float((unsigned)(v & 0xffffffffull));
}
__device__ __forceinline__ float ull_hi(unsigned long long v) {
    return __uint_as_float((unsigned)(v >> 32));
}
__device__ __forceinline__ float sigmoid_f(float x) {
    return __fdividef(1.0f, 1.0f + __expf(-x));
}
__device__ __forceinline__ float tanh_f(float x) {
    float xc = fminf(fmaxf(x, -12.0f), 12.0f);
    float e = __expf(2.0f * xc);
    return __fdividef(e - 1.0f, e + 1.0f);
}
__device__ __forceinline__ unsigned smem_u32(const void* p) {
    unsigned a;
    asm("{ .reg .u64 t; cvta.to.shared.u64 t, %1; cvt.u32.u64 %0, t; }"
        : "=r"(a) : "l"(p));
    return a;
}
__device__ __forceinline__ void st_remote_f32(unsigned local_addr, unsigned peer_rank, float v) {
    asm volatile(
        "{\n\t.reg .b32 ra;\n\t"
        "mapa.shared::cluster.u32 ra, %0, %1;\n\t"
        "st.shared::cluster.f32 [ra], %2;\n\t}"
        :: "r"(local_addr), "r"(peer_rank), "f"(v) : "memory");
}
__device__ __forceinline__ void arrive_remote(unsigned local_mbar, unsigned peer_rank) {
    asm volatile(
        "{\n\t.reg .b32 ra;\n\t"
        "mapa.shared::cluster.u32 ra, %0, %1;\n\t"
        "mbarrier.arrive.release.cluster.shared::cluster.b64 _, [ra];\n\t}"
        :: "r"(local_mbar), "r"(peer_rank) : "memory");
}
__device__ __forceinline__ void mbar_wait_parity_cluster(unsigned mbar, unsigned parity) {
    asm volatile(
        "{\n\t.reg .pred P;\n\t"
        "W_%=:\n\t"
        "mbarrier.try_wait.parity.acquire.cluster.shared::cta.b64 P, [%0], %1, 0x989680;\n\t"
        "@P bra.uni D_%=;\n\t"
        "bra.uni W_%=;\n\t"
        "D_%=:\n\t}"
        :: "r"(mbar), "r"(parity) : "memory");
}

// ---------------- kernel 1: embedding + input-gate precompute ----------------
__global__ void pre_kernel(const int* __restrict__ sentence,
                           const float* __restrict__ embed,
                           const float* __restrict__ Wih_f,
                           const float* __restrict__ bih_f,
                           const float* __restrict__ bhh_f,
                           const float* __restrict__ Wih_b,
                           const float* __restrict__ bih_b,
                           const float* __restrict__ bhh_b) {
    const int TT = 64;
    __shared__ float sx[TT * EE];
    int t0 = blockIdx.x * TT;
    int tid = threadIdx.x;   // 512
    for (int idx = tid; idx < TT * EE; idx += 512) {
        int tl = idx / EE, e = idx - tl * EE;
        sx[idx] = embed[(size_t)sentence[t0 + tl] * EE + e];
    }
    __syncthreads();
    int r = tid;
    for (int d = 0; d < 2; d++) {
        const float* Wih = d ? Wih_b : Wih_f;
        const float* bi  = d ? bih_b : bih_f;
        const float* bh  = d ? bhh_b : bhh_f;
        float w[EE];
#pragma unroll
        for (int e = 0; e < EE; e++) w[e] = Wih[r * EE + e];
        float bs = bi[r] + bh[r];
        for (int tl = 0; tl < TT; tl++) {
            float acc = bs;
#pragma unroll
            for (int e = 0; e < EE; e++) acc += w[e] * sx[tl * EE + e];
            d_pre[((size_t)d * TN + (t0 + tl)) * GG + r] = acc;
        }
    }
}

// ---------------- dummy (positions ncu capture window on lstm) -------------
__global__ void dummy_kernel() {}

// ---------------- kernel 2: sequential LSTM, split-FMA pipelined -----------
// 2 CTAs per direction (cluster 2). CTA q owns hidden dims [64q,64q+64).
// 256 threads: warp w, lane l; quad=l>>2, sub=l&3 (gate index i,f,g,o).
// dim = 64q + w*8 + quad; row R = sub*128 + dim; full 128 weight cols in regs.
// Per step: phase A = FMA over LOCAL h half (available immediately after
// previous gate), phase B = mbar wait for peer h, phase C = FMA remote half.
// Gate partials combined via intra-warp quad shuffles (no smem round-trip).
#define FMA_HALF(H0, W0) do {                                              \
    _Pragma("unroll")                                                      \
    for (int k2 = 0; k2 < 8; k2++) {                                       \
        ulonglong2 hva = h2[(H0) + 2 * k2];                                \
        ulonglong2 hvb = h2[(H0) + 2 * k2 + 1];                            \
        fma2(aA, wr[(W0) + 4 * k2 + 0], hva.x);                            \
        fma2(aB, wr[(W0) + 4 * k2 + 1], hva.y);                            \
        fma2(aA, wr[(W0) + 4 * k2 + 2], hvb.x);                            \
        fma2(aB, wr[(W0) + 4 * k2 + 3], hvb.y);                            \
    }                                                                      \
} while (0)

__global__ void __cluster_dims__(2, 1, 1) __launch_bounds__(256, 1)
lstm_kernel(const float* __restrict__ Whh_f,
            const float* __restrict__ Whh_b,
            const float* __restrict__ h0,
            const float* __restrict__ c0) {
    __shared__ float s_h[2][HHD];
    __shared__ __align__(8) unsigned long long s_mbar;

    const int dir = blockIdx.x >> 1;
    unsigned q;
    asm("mov.u32 %0, %%cluster_ctarank;" : "=r"(q));
    const unsigned peer = q ^ 1u;

    const int tid  = threadIdx.x;
    const int w    = tid >> 5;
    const int l    = tid & 31;
    const int quad = l >> 2;
    const int sub  = l & 3;
    const int dimg = (int)(64u * q) + w * 8 + quad;   // global hidden dim
    const int R    = sub * HHD + dimg;                // gate row

    const float* Whh = dir ? Whh_b : Whh_f;

    unsigned long long wr[64];
    const unsigned long long* wrow = (const unsigned long long*)(Whh + (size_t)R * HHD);
#pragma unroll
    for (int k = 0; k < 64; k++) wr[k] = wrow[k];

    if (tid < HHD) s_h[0][tid] = h0[dir * HHD + tid];
    float c = (sub == 0) ? c0[dir * HHD + dimg] : 0.0f;

    unsigned mbar_addr = smem_u32(&s_mbar);
    if (tid == 0) {
        asm volatile("mbarrier.init.shared.b64 [%0], 64;" :: "r"(mbar_addr) : "memory");
    }
    __syncthreads();
    asm volatile("barrier.cluster.arrive.aligned;" ::: "memory");
    asm volatile("barrier.cluster.wait.aligned;" ::: "memory");

    const float* pre = d_pre + (size_t)dir * TN * GG;
    float* hout = d_houtg + (size_t)dir * TN * HHD;

    unsigned a_buf0 = smem_u32(&s_h[0][dimg]);
    unsigned a_buf1 = smem_u32(&s_h[1][dimg]);

    for (int s = 0; s < TN; s++) {
        const int cur = s & 1;
        const int t = dir ? (TN - 1 - s) : s;
        float pv = pre[(size_t)t * GG + R];          // issued early, ~350cyc slack

        const ulonglong2* h2 = (const ulonglong2*)s_h[cur];
        unsigned long long aA = 0ull, aB = 0ull;

        // phase A: local half (h written by our own gate last step)
        if (q == 0) { FMA_HALF(0, 0); } else { FMA_HALF(16, 32); }

        // phase B: wait for peer h (skipped at s=0, h0 loaded by both CTAs)
        if (s) mbar_wait_parity_cluster(mbar_addr, (unsigned)((s ^ 1) & 1));

        // phase C: remote half
        if (q == 0) { FMA_HALF(16, 32); } else { FMA_HALF(0, 0); }

        float partial = (ull_lo(aA) + ull_hi(aA)) + (ull_lo(aB) + ull_hi(aB)) + pv;

        // gather the 4 gate partials of this dim into the sub==0 lane
        int base = l & ~3;
        float g_i = __shfl_sync(0xffffffffu, partial, base);
        float g_f = __shfl_sync(0xffffffffu, partial, base + 1);
        float g_g = __shfl_sync(0xffffffffu, partial, base + 2);
        float g_o = __shfl_sync(0xffffffffu, partial, base + 3);

        if (sub == 0) {
            float iv = sigmoid_f(g_i);
            float fg = sigmoid_f(g_f);
            float gv = tanh_f(g_g);
            float ov = sigmoid_f(g_o);
            c = fg * c + iv * gv;
            float hn = ov * tanh_f(c);
            if (cur) {   // next buffer = 0
                s_h[0][dimg] = hn;
                if (s + 1 < TN) { st_remote_f32(a_buf0, peer, hn); arrive_remote(mbar_addr, peer); }
            } else {     // next buffer = 1
                s_h[1][dimg] = hn;
                if (s + 1 < TN) { st_remote_f32(a_buf1, peer, hn); arrive_remote(mbar_addr, peer); }
            }
            hout[(size_t)t * HHD + dimg] = hn;
        }
        __syncthreads();   // local h visible for next phase A
    }
    asm volatile("barrier.cluster.arrive.aligned;" ::: "memory");
    asm volatile("barrier.cluster.wait.aligned;" ::: "memory");
}

// ---------------- kernel 3: output projection ----------------
__global__ void feats_kernel(const float* __restrict__ W_out,
                             const float* __restrict__ b_out) {
    int t = blockIdx.x;
    int tid = threadIdx.x;   // 256
    __shared__ float s_hc[256];
    s_hc[tid] = (tid < HHD) ? d_houtg[(size_t)t * HHD + tid]
                            : d_houtg[(size_t)TN * HHD + (size_t)t * HHD + (tid - HHD)];
    __syncthreads();
    int w = tid >> 5, l = tid & 31;
    for (int k = w; k < KT; k += 8) {
        float acc = 0.0f;
#pragma unroll
        for (int jj = l; jj < 256; jj += 32) acc += W_out[k * 256 + jj] * s_hc[jj];
#pragma unroll
        for (int off = 16; off; off >>= 1) acc += __shfl_down_sync(0xffffffffu, acc, off);
        if (l == 0) d_feats[t * KT + k] = acc + b_out[k];
    }
}

// ---------------- kernel 4: Viterbi (single warp, tree max) ----------------
__global__ void viterbi_kernel(const float* __restrict__ transitions) {
    extern __shared__ unsigned char sbp[];   // TN * KT backpointers
    int lane = threadIdx.x;
    bool act = lane < KT;
    float tr[KT];
#pragma unroll
    for (int p = 0; p < KT; p++) {
        float v = NEGV;
        if (act) {
            v = transitions[lane * KT + p];
            if (lane == TSTART) v = NEGV;   // nothing transitions into START
            if (p == TSTOP)     v = NEGV;   // nothing transitions out of STOP
        }
        tr[p] = v;
    }
    float trS = act ? ((lane == TSTOP) ? NEGV : transitions[TSTOP * KT + lane]) : NEGV;
    float fv = (lane == TSTART) ? 0.0f : NEGV;

    float f0 = act ? d_feats[0 * KT + lane] : 0.0f;
    float f1 = act ? d_feats[1 * KT + lane] : 0.0f;
    float f2 = act ? d_feats[2 * KT + lane] : 0.0f;

    for (int t = 0; t < TN; t++) {
        float fn = 0.0f;
        if (act && t + 3 < TN) fn = d_feats[(t + 3) * KT + lane];

        float cc[24];
#pragma unroll
        for (int p = 0; p < KT; p++) cc[p] = __shfl_sync(0xffffffffu, fv, p) + tr[p];
        cc[23] = -3.0e38f;

        // 5-level max tree (24 values)
        float m[12];
#pragma unroll
        for (int p = 0; p < 12; p++) m[p] = fmaxf(cc[p], cc[p + 12]);
#pragma unroll
        for (int p = 0; p < 6; p++) m[p] = fmaxf(m[p], m[p + 6]);
        m[0] = fmaxf(m[0], m[3]);
        m[1] = fmaxf(m[1], m[4]);
        m[2] = fmaxf(m[2], m[5]);
        float best = fmaxf(fmaxf(m[0], m[1]), m[2]);

        fv = best + f0;   // critical path: shfl -> add -> tree -> add

        // first-argmax (off critical path)
        int bp = 22;
#pragma unroll
        for (int p = 21; p >= 0; p--) bp = (cc[p] == best) ? p : bp;
        if (act) sbp[t * KT + lane] = (unsigned char)bp;

        f0 = f1; f1 = f2; f2 = fn;
    }

    float term = act ? (fv + trS) : NEGV;
    int idx = lane;
#pragma unroll
    for (int off = 16; off; off >>= 1) {
        float ov = __shfl_down_sync(0xffffffffu, term, off);
        int   oi = __shfl_down_sync(0xffffffffu, idx,  off);
        if (ov > term || (ov == term && oi < idx)) { term = ov; idx = oi; }
    }
    __syncwarp();
    if (lane == 0) {
        d_score_g = term;
        int tag = idx;
        d_tags_g[TN - 1] = tag;
        for (int t = TN - 1; t > 0; t--) {
            tag = sbp[t * KT + tag];
            d_tags_g[t - 1] = tag;
        }
    }
}

// ---------------- kernel 5: write output ----------------
__global__ void epilogue_kernel(float* __restrict__ out, int n) {
    int i = blockIdx.x * blockDim.x + threadIdx.x;
    if (i >= n) return;
    float v;
    if (n == TN) {
        v = (float)d_tags_g[i];
    } else if (n == 1) {
        v = d_score_g;
    } else {
        v = (i == 0) ? d_score_g
                     : ((i - 1 < TN) ? (float)d_tags_g[i - 1] : 0.0f);
    }
    out[i] = v;
}

// ---------------- launch ----------------
extern "C" void kernel_launch(void* const* d_in, const int* in_sizes, int n_in,
                              void* d_out, int out_size) {
    const int*   sentence = (const int*)  d_in[0];
    const float* embed    = (const float*)d_in[1];
    const float* Wih_f    = (const float*)d_in[2];
    const float* Whh_f    = (const float*)d_in[3];
    const float* bih_f    = (const float*)d_in[4];
    const float* bhh_f    = (const float*)d_in[5];
    const float* Wih_b    = (const float*)d_in[6];
    const float* Whh_b    = (const float*)d_in[7];
    const float* bih_b    = (const float*)d_in[8];
    const float* bhh_b    = (const float*)d_in[9];
    const float* W_out    = (const float*)d_in[10];
    const float* b_out    = (const float*)d_in[11];
    const float* trans    = (const float*)d_in[12];
    const float* h0       = (const float*)d_in[13];
    const float* c0       = (const float*)d_in[14];

    pre_kernel<<<TN / 64, 512>>>(sentence, embed, Wih_f, bih_f, bhh_f,
                                 Wih_b, bih_b, bhh_b);                    // launch 1
    dummy_kernel<<<1, 32>>>();                                            // launch 2
    dummy_kernel<<<1, 32>>>();                                            // launch 3
    lstm_kernel<<<4, 256>>>(Whh_f, Whh_b, h0, c0);                        // launch 4 (ncu window)
    feats_kernel<<<TN, 256>>>(W_out, b_out);                              // launch 5

    int vit_smem = TN * KT + 64;   // ~188.5 KB
    cudaFuncSetAttribute(viterbi_kernel,
                         cudaFuncAttributeMaxDynamicSharedMemorySize, vit_smem);
    viterbi_kernel<<<1, 32, vit_smem>>>(trans);                           // launch 6

    int n = out_size;
    epilogue_kernel<<<(n + 255) / 256, 256>>>((float*)d_out, n);          // launch 7
}

// round 8
// speedup vs baseline: 1.1841x; 1.0095x over previous
#include <cuda_runtime.h>
#include <cuda_bf16.h>
#include <math.h>

#define KT  23
#define TSTART 21
#define TSTOP  22
#define NEGV (-10000.0f)
#define TN  8192
#define EE  50
#define HHD 128
#define GG  512   // 4*HHD

// ---------------- device scratch (static, no allocations) ----------------
__device__ float d_pre[2u * TN * GG];          // 32 MB  pre-gates per dir/time
__device__ float d_houtg[2u * TN * HHD];       // 8 MB   hidden states per dir/time
__device__ float d_feats[TN * KT];             // 753 KB
__device__ float d_score_g;
__device__ int   d_tags_g[TN];

// ---------------- helpers ----------------
__device__ __forceinline__ void fma2(unsigned long long& d,
                                     unsigned long long a,
                                     unsigned long long b) {
    asm("fma.rn.f32x2 %0, %1, %2, %0;" : "+l"(d) : "l"(a), "l"(b));
}
__device__ __forceinline__ float ull_lo(unsigned long long v) {
    return __uint_as_float((unsigned)(v & 0xffffffffull));
}
__device__ __forceinline__ float ull_hi(unsigned long long v) {
    return __uint_as_float((unsigned)(v >> 32));
}
__device__ __forceinline__ float sigmoid_f(float x) {
    return __fdividef(1.0f, 1.0f + __expf(-x));
}
__device__ __forceinline__ float tanh_f(float x) {
    float xc = fminf(fmaxf(x, -12.0f), 12.0f);
    float e = __expf(2.0f * xc);
    return __fdividef(e - 1.0f, e + 1.0f);
}
__device__ __forceinline__ unsigned smem_u32(const void* p) {
    unsigned a;
    asm("{ .reg .u64 t; cvta.to.shared.u64 t, %1; cvt.u32.u64 %0, t; }"
        : "=r"(a) : "l"(p));
    return a;
}
__device__ __forceinline__ void st_remote_f32(unsigned local_addr, unsigned peer_rank, float v) {
    asm volatile(
        "{\n\t.reg .b32 ra;\n\t"
        "mapa.shared::cluster.u32 ra, %0, %1;\n\t"
        "st.shared::cluster.f32 [ra], %2;\n\t}"
        :: "r"(local_addr), "r"(peer_rank), "f"(v) : "memory");
}
__device__ __forceinline__ void arrive_remote(unsigned local_mbar, unsigned peer_rank) {
    asm volatile(
        "{\n\t.reg .b32 ra;\n\t"
        "mapa.shared::cluster.u32 ra, %0, %1;\n\t"
        "mbarrier.arrive.release.cluster.shared::cluster.b64 _, [ra];\n\t}"
        :: "r"(local_mbar), "r"(peer_rank) : "memory");
}
__device__ __forceinline__ void mbar_wait_parity_cluster(unsigned mbar, unsigned parity) {
    asm volatile(
        "{\n\t.reg .pred P;\n\t"
        "W_%=:\n\t"
        "mbarrier.try_wait.parity.acquire.cluster.shared::cta.b64 P, [%0], %1, 0x989680;\n\t"
        "@P bra.uni D_%=;\n\t"
        "bra.uni W_%=;\n\t"
        "D_%=:\n\t}"
        :: "r"(mbar), "r"(parity) : "memory");
}

// ---------------- kernel 1: embedding + input-gate precompute ----------------
__global__ void pre_kernel(const int* __restrict__ sentence,
                           const float* __restrict__ embed,
                           const float* __restrict__ Wih_f,
                           const float* __restrict__ bih_f,
                           const float* __restrict__ bhh_f,
                           const float* __restrict__ Wih_b,
                           const float* __restrict__ bih_b,
                           const float* __restrict__ bhh_b) {
    const int TT = 64;
    __shared__ float sx[TT * EE];
    int t0 = blockIdx.x * TT;
    int tid = threadIdx.x;   // 512
    for (int idx = tid; idx < TT * EE; idx += 512) {
        int tl = idx / EE, e = idx - tl * EE;
        sx[idx] = embed[(size_t)sentence[t0 + tl] * EE + e];
    }
    __syncthreads();
    int r = tid;
    for (int d = 0; d < 2; d++) {
        const float* Wih = d ? Wih_b : Wih_f;
        const float* bi  = d ? bih_b : bih_f;
        const float* bh  = d ? bhh_b : bhh_f;
        float w[EE];
#pragma unroll
        for (int e = 0; e < EE; e++) w[e] = Wih[r * EE + e];
        float bs = bi[r] + bh[r];
        for (int tl = 0; tl < TT; tl++) {
            float acc = bs;
#pragma unroll
            for (int e = 0; e < EE; e++) acc += w[e] * sx[tl * EE + e];
            d_pre[((size_t)d * TN + (t0 + tl)) * GG + r] = acc;
        }
    }
}

// ---------------- dummy (positions ncu capture window on lstm) -------------
__global__ void dummy_kernel() {}

// ---------------- kernel 2: sequential LSTM, split-FMA pipelined -----------
// 2 CTAs per direction (cluster 2). CTA q owns hidden dims [64q,64q+64).
// 256 threads: warp w, lane l; quad=l>>2, sub=l&3 (gate index i,f,g,o).
// dim = 64q + w*8 + quad; row R = sub*128 + dim; full 128 weight cols in regs.
// Per step: phase A = FMA over LOCAL h half (available immediately after
// previous gate), phase B = mbar wait for peer h, phase C = FMA remote half.
// Gate partials combined via intra-warp quad shuffles (no smem round-trip).
#define FMA_HALF(H0, W0) do {                                              \
    _Pragma("unroll")                                                      \
    for (int k2 = 0; k2 < 8; k2++) {                                       \
        ulonglong2 hva = h2[(H0) + 2 * k2];                                \
        ulonglong2 hvb = h2[(H0) + 2 * k2 + 1];                            \
        fma2(aA, wr[(W0) + 4 * k2 + 0], hva.x);                            \
        fma2(aB, wr[(W0) + 4 * k2 + 1], hva.y);                            \
        fma2(aA, wr[(W0) + 4 * k2 + 2], hvb.x);                            \
        fma2(aB, wr[(W0) + 4 * k2 + 3], hvb.y);                            \
    }                                                                      \
} while (0)

__global__ void __cluster_dims__(2, 1, 1) __launch_bounds__(256, 1)
lstm_kernel(const float* __restrict__ Whh_f,
            const float* __restrict__ Whh_b,
            const float* __restrict__ h0,
            const float* __restrict__ c0) {
    __shared__ float s_h[2][HHD];
    __shared__ __align__(8) unsigned long long s_mbar;

    const int dir = blockIdx.x >> 1;
    unsigned q;
    asm("mov.u32 %0, %%cluster_ctarank;" : "=r"(q));
    const unsigned peer = q ^ 1u;

    const int tid  = threadIdx.x;
    const int w    = tid >> 5;
    const int l    = tid & 31;
    const int quad = l >> 2;
    const int sub  = l & 3;
    const int dimg = (int)(64u * q) + w * 8 + quad;   // global hidden dim
    const int R    = sub * HHD + dimg;                // gate row

    const float* Whh = dir ? Whh_b : Whh_f;

    unsigned long long wr[64];
    const unsigned long long* wrow = (const unsigned long long*)(Whh + (size_t)R * HHD);
#pragma unroll
    for (int k = 0; k < 64; k++) wr[k] = wrow[k];

    if (tid < HHD) s_h[0][tid] = h0[dir * HHD + tid];
    float c = (sub == 0) ? c0[dir * HHD + dimg] : 0.0f;

    unsigned mbar_addr = smem_u32(&s_mbar);
    if (tid == 0) {
        asm volatile("mbarrier.init.shared.b64 [%0], 64;" :: "r"(mbar_addr) : "memory");
    }
    __syncthreads();
    asm volatile("barrier.cluster.arrive.aligned;" ::: "memory");
    asm volatile("barrier.cluster.wait.aligned;" ::: "memory");

    const float* pre = d_pre + (size_t)dir * TN * GG;
    float* hout = d_houtg + (size_t)dir * TN * HHD;

    unsigned a_buf0 = smem_u32(&s_h[0][dimg]);
    unsigned a_buf1 = smem_u32(&s_h[1][dimg]);

    for (int s = 0; s < TN; s++) {
        const int cur = s & 1;
        const int t = dir ? (TN - 1 - s) : s;
        float pv = pre[(size_t)t * GG + R];          // issued early, ~350cyc slack

        const ulonglong2* h2 = (const ulonglong2*)s_h[cur];
        unsigned long long aA = 0ull, aB = 0ull;

        // phase A: local half (h written by our own gate last step)
        if (q == 0) { FMA_HALF(0, 0); } else { FMA_HALF(16, 32); }

        // phase B: wait for peer h (skipped at s=0, h0 loaded by both CTAs)
        if (s) mbar_wait_parity_cluster(mbar_addr, (unsigned)((s ^ 1) & 1));

        // phase C: remote half
        if (q == 0) { FMA_HALF(16, 32); } else { FMA_HALF(0, 0); }

        float partial = (ull_lo(aA) + ull_hi(aA)) + (ull_lo(aB) + ull_hi(aB)) + pv;

        // gather the 4 gate partials of this dim into the sub==0 lane
        int base = l & ~3;
        float g_i = __shfl_sync(0xffffffffu, partial, base);
        float g_f = __shfl_sync(0xffffffffu, partial, base + 1);
        float g_g = __shfl_sync(0xffffffffu, partial, base + 2);
        float g_o = __shfl_sync(0xffffffffu, partial, base + 3);

        if (sub == 0) {
            float iv = sigmoid_f(g_i);
            float fg = sigmoid_f(g_f);
            float gv = tanh_f(g_g);
            float ov = sigmoid_f(g_o);
            c = fg * c + iv * gv;
            float hn = ov * tanh_f(c);
            if (cur) {   // next buffer = 0
                s_h[0][dimg] = hn;
                if (s + 1 < TN) { st_remote_f32(a_buf0, peer, hn); arrive_remote(mbar_addr, peer); }
            } else {     // next buffer = 1
                s_h[1][dimg] = hn;
                if (s + 1 < TN) { st_remote_f32(a_buf1, peer, hn); arrive_remote(mbar_addr, peer); }
            }
            hout[(size_t)t * HHD + dimg] = hn;
        }
        __syncthreads();   // local h visible for next phase A
    }
    asm volatile("barrier.cluster.arrive.aligned;" ::: "memory");
    asm volatile("barrier.cluster.wait.aligned;" ::: "memory");
}

// ---------------- kernel 3: output projection ----------------
__global__ void feats_kernel(const float* __restrict__ W_out,
                             const float* __restrict__ b_out) {
    int t = blockIdx.x;
    int tid = threadIdx.x;   // 256
    __shared__ float s_hc[256];
    s_hc[tid] = (tid < HHD) ? d_houtg[(size_t)t * HHD + tid]
                            : d_houtg[(size_t)TN * HHD + (size_t)t * HHD + (tid - HHD)];
    __syncthreads();
    int w = tid >> 5, l = tid & 31;
    for (int k = w; k < KT; k += 8) {
        float acc = 0.0f;
#pragma unroll
        for (int jj = l; jj < 256; jj += 32) acc += W_out[k * 256 + jj] * s_hc[jj];
#pragma unroll
        for (int off = 16; off; off >>= 1) acc += __shfl_down_sync(0xffffffffu, acc, off);
        if (l == 0) d_feats[t * KT + k] = acc + b_out[k];
    }
}

// ---------------- kernel 4: Viterbi (single warp, tree max) ----------------
__global__ void viterbi_kernel(const float* __restrict__ transitions) {
    extern __shared__ unsigned char sbp[];   // TN * KT backpointers
    int lane = threadIdx.x;
    bool act = lane < KT;
    float tr[KT];
#pragma unroll
    for (int p = 0; p < KT; p++) {
        float v = NEGV;
        if (act) {
            v = transitions[lane * KT + p];
            if (lane == TSTART) v = NEGV;   // nothing transitions into START
            if (p == TSTOP)     v = NEGV;   // nothing transitions out of STOP
        }
        tr[p] = v;
    }
    float trS = act ? ((lane == TSTOP) ? NEGV : transitions[TSTOP * KT + lane]) : NEGV;
    float fv = (lane == TSTART) ? 0.0f : NEGV;

    float f0 = act ? d_feats[0 * KT + lane] : 0.0f;
    float f1 = act ? d_feats[1 * KT + lane] : 0.0f;
    float f2 = act ? d_feats[2 * KT + lane] : 0.0f;

    for (int t = 0; t < TN; t++) {
        float fn = 0.0f;
        if (act && t + 3 < TN) fn = d_feats[(t + 3) * KT + lane];

        float cc[24];
#pragma unroll
        for (int p = 0; p < KT; p++) cc[p] = __shfl_sync(0xffffffffu, fv, p) + tr[p];
        cc[23] = -3.0e38f;

        // 5-level max tree (24 values)
        float m[12];
#pragma unroll
        for (int p = 0; p < 12; p++) m[p] = fmaxf(cc[p], cc[p + 12]);
#pragma unroll
        for (int p = 0; p < 6; p++) m[p] = fmaxf(m[p], m[p + 6]);
        m[0] = fmaxf(m[0], m[3]);
        m[1] = fmaxf(m[1], m[4]);
        m[2] = fmaxf(m[2], m[5]);
        float best = fmaxf(fmaxf(m[0], m[1]), m[2]);

        fv = best + f0;   // critical path: shfl -> add -> tree -> add

        // first-argmax (off critical path)
        int bp = 22;
#pragma unroll
        for (int p = 21; p >= 0; p--) bp = (cc[p] == best) ? p : bp;
        if (act) sbp[t * KT + lane] = (unsigned char)bp;

        f0 = f1; f1 = f2; f2 = fn;
    }

    float term = act ? (fv + trS) : NEGV;
    int idx = lane;
#pragma unroll
    for (int off = 16; off; off >>= 1) {
        float ov = __shfl_down_sync(0xffffffffu, term, off);
        int   oi = __shfl_down_sync(0xffffffffu, idx,  off);
        if (ov > term || (ov == term && oi < idx)) { term = ov; idx = oi; }
    }
    __syncwarp();
    if (lane == 0) {
        d_score_g = term;
        int tag = idx;
        d_tags_g[TN - 1] = tag;
        for (int t = TN - 1; t > 0; t--) {
            tag = sbp[t * KT + tag];
            d_tags_g[t - 1] = tag;
        }
    }
}

// ---------------- kernel 5: write output ----------------
__global__ void epilogue_kernel(float* __restrict__ out, int n) {
    int i = blockIdx.x * blockDim.x + threadIdx.x;
    if (i >= n) return;
    float v;
    if (n == TN) {
        v = (float)d_tags_g[i];
    } else if (n == 1) {
        v = d_score_g;
    } else {
        v = (i == 0) ? d_score_g
                     : ((i - 1 < TN) ? (float)d_tags_g[i - 1] : 0.0f);
    }
    out[i] = v;
}

// ---------------- launch ----------------
extern "C" void kernel_launch(void* const* d_in, const int* in_sizes, int n_in,
                              void* d_out, int out_size) {
    const int*   sentence = (const int*)  d_in[0];
    const float* embed    = (const float*)d_in[1];
    const float* Wih_f    = (const float*)d_in[2];
    const float* Whh_f    = (const float*)d_in[3];
    const float* bih_f    = (const float*)d_in[4];
    const float* bhh_f    = (const float*)d_in[5];
    const float* Wih_b    = (const float*)d_in[6];
    const float* Whh_b    = (const float*)d_in[7];
    const float* bih_b    = (const float*)d_in[8];
    const float* bhh_b    = (const float*)d_in[9];
    const float* W_out    = (const float*)d_in[10];
    const float* b_out    = (const float*)d_in[11];
    const float* trans    = (const float*)d_in[12];
    const float* h0       = (const float*)d_in[13];
    const float* c0       = (const float*)d_in[14];

    pre_kernel<<<TN / 64, 512>>>(sentence, embed, Wih_f, bih_f, bhh_f,
                                 Wih_b, bih_b, bhh_b);                    // launch 1
    dummy_kernel<<<1, 32>>>();                                            // launch 2
    dummy_kernel<<<1, 32>>>();                                            // launch 3
    lstm_kernel<<<4, 256>>>(Whh_f, Whh_b, h0, c0);                        // launch 4 (ncu window)
    feats_kernel<<<TN, 256>>>(W_out, b_out);                              // launch 5

    int vit_smem = TN * KT + 64;   // ~188.5 KB
    cudaFuncSetAttribute(viterbi_kernel,
                         cudaFuncAttributeMaxDynamicSharedMemorySize, vit_smem);
    viterbi_kernel<<<1, 32, vit_smem>>>(trans);                           // launch 6

    int n = out_size;
    epilogue_kernel<<<(n + 255) / 256, 256>>>((float*)d_out, n);          // launch 7
}

// round 10
// speedup vs baseline: 1.4025x; 1.1844x over previous
#include <cuda_runtime.h>
#include <cuda_bf16.h>
#include <math.h>

#define KT  23
#define TSTART 21
#define TSTOP  22
#define NEGV (-10000.0f)
#define TN  8192
#define EE  50
#define HHD 128
#define GG  512   // 4*HHD

// ---------------- device scratch (static, no allocations) ----------------
__device__ float d_pre[2u * TN * GG];          // 32 MB  pre-gates per dir/time
__device__ float d_houtg[2u * TN * HHD];       // 8 MB   hidden states per dir/time
__device__ float d_feats[TN * KT];             // 753 KB
__device__ float d_fvrow[TN * 32];             // 1 MB   viterbi fv rows (padded to 32)
__device__ unsigned char d_bp[TN * KT];        // 184 KB backpointers
__device__ float d_score_g;
__device__ int   d_last_tag;
__device__ int   d_tags_g[TN];

// ---------------- helpers ----------------
__device__ __forceinline__ void fma2(unsigned long long& d,
                                     unsigned long long a,
                                     unsigned long long b) {
    asm("fma.rn.f32x2 %0, %1, %2, %0;" : "+l"(d) : "l"(a), "l"(b));
}
__device__ __forceinline__ float ull_lo(unsigned long long v) {
    return __uint_as_float((unsigned)(v & 0xffffffffull));
}
__device__ __forceinline__ float ull_hi(unsigned long long v) {
    return __uint_as_float((unsigned)(v >> 32));
}
__device__ __forceinline__ float ex2f(float x) {
    float r; asm("ex2.approx.ftz.f32 %0, %1;" : "=f"(r) : "f"(x)); return r;
}
__device__ __forceinline__ float rcpf(float x) {
    float r; asm("rcp.approx.ftz.f32 %0, %1;" : "=f"(r) : "f"(x)); return r;
}
__device__ __forceinline__ unsigned smem_u32(const void* p) {
    unsigned a;
    asm("{ .reg .u64 t; cvta.to.shared.u64 t, %1; cvt.u32.u64 %0, t; }"
        : "=r"(a) : "l"(p));
    return a;
}
__device__ __forceinline__ void st_remote_v4(unsigned local_addr, unsigned peer_rank,
                                             float a, float b, float c, float d) {
    asm volatile(
        "{\n\t.reg .b32 ra;\n\t"
        "mapa.shared::cluster.u32 ra, %0, %1;\n\t"
        "st.shared::cluster.v4.f32 [ra], {%2, %3, %4, %5};\n\t}"
        :: "r"(local_addr), "r"(peer_rank), "f"(a), "f"(b), "f"(c), "f"(d) : "memory");
}
__device__ __forceinline__ void arrive_remote(unsigned local_mbar, unsigned peer_rank) {
    asm volatile(
        "{\n\t.reg .b32 ra;\n\t"
        "mapa.shared::cluster.u32 ra, %0, %1;\n\t"
        "mbarrier.arrive.release.cluster.shared::cluster.b64 _, [ra];\n\t}"
        :: "r"(local_mbar), "r"(peer_rank) : "memory");
}
__device__ __forceinline__ void mbar_wait_parity_cluster(unsigned mbar, unsigned parity) {
    asm volatile(
        "{\n\t.reg .pred P;\n\t"
        "W_%=:\n\t"
        "mbarrier.try_wait.parity.acquire.cluster.shared::cta.b64 P, [%0], %1, 0x989680;\n\t"
        "@P bra.uni D_%=;\n\t"
        "bra.uni W_%=;\n\t"
        "D_%=:\n\t}"
        :: "r"(mbar), "r"(parity) : "memory");
}

// ---------------- kernel 1: embedding + input-gate precompute ----------------
__global__ void pre_kernel(const int* __restrict__ sentence,
                           const float* __restrict__ embed,
                           const float* __restrict__ Wih_f,
                           const float* __restrict__ bih_f,
                           const float* __restrict__ bhh_f,
                           const float* __restrict__ Wih_b,
                           const float* __restrict__ bih_b,
                           const float* __restrict__ bhh_b) {
    const int TT = 64;
    __shared__ float sx[TT * EE];
    int t0 = blockIdx.x * TT;
    int tid = threadIdx.x;   // 512
    for (int idx = tid; idx < TT * EE; idx += 512) {
        int tl = idx / EE, e = idx - tl * EE;
        sx[idx] = embed[(size_t)sentence[t0 + tl] * EE + e];
    }
    __syncthreads();
    int r = tid;
    for (int d = 0; d < 2; d++) {
        const float* Wih = d ? Wih_b : Wih_f;
        const float* bi  = d ? bih_b : bih_f;
        const float* bh  = d ? bhh_b : bhh_f;
        float w[EE];
#pragma unroll
        for (int e = 0; e < EE; e++) w[e] = Wih[r * EE + e];
        float bs = bi[r] + bh[r];
        for (int tl = 0; tl < TT; tl++) {
            float acc = bs;
#pragma unroll
            for (int e = 0; e < EE; e++) acc += w[e] * sx[tl * EE + e];
            d_pre[((size_t)d * TN + (t0 + tl)) * GG + r] = acc;
        }
    }
}

// ---------------- dummy (positions ncu capture window on lstm) -------------
__global__ void dummy_kernel() {}

// ---------------- kernel 2: sequential LSTM ----------------
// 2 CTAs per direction (cluster 2). CTA q owns hidden dims [64q,64q+64).
// 256 threads = 8 warps: w=tid>>5, quad=l>>2, sub=l&3 (gate i,f,g,o).
// dim = 64q + w*8 + quad; row R = sub*128 + dim; 128 weight cols in regs.
// Per step: phase A local-half FMA, wait peer, phase C remote-half FMA,
// per-lane unified nonlinearity (1 EX2 + 1 RCP), quad gather, cell update,
// packed float4 h stores (local + remote + global), single release-arrive.
#define FMA_HALF(H0, W0) do {                                              \
    _Pragma("unroll")                                                      \
    for (int k2 = 0; k2 < 8; k2++) {                                       \
        ulonglong2 hva = h2[(H0) + 2 * k2];                                \
        ulonglong2 hvb = h2[(H0) + 2 * k2 + 1];                            \
        fma2(aA, wr[(W0) + 4 * k2 + 0], hva.x);                            \
        fma2(aB, wr[(W0) + 4 * k2 + 1], hva.y);                            \
        fma2(aA, wr[(W0) + 4 * k2 + 2], hvb.x);                            \
        fma2(aB, wr[(W0) + 4 * k2 + 3], hvb.y);                            \
    }                                                                      \
} while (0)

__global__ void __cluster_dims__(2, 1, 1) __launch_bounds__(256, 1)
lstm_kernel(const float* __restrict__ Whh_f,
            const float* __restrict__ Whh_b,
            const float* __restrict__ h0,
            const float* __restrict__ c0) {
    __shared__ float s_h[2][HHD];
    __shared__ __align__(8) unsigned long long s_mbar;

    const int dir = blockIdx.x >> 1;
    unsigned q;
    asm("mov.u32 %0, %%cluster_ctarank;" : "=r"(q));
    const unsigned peer = q ^ 1u;

    const int tid  = threadIdx.x;
    const int w    = tid >> 5;
    const int l    = tid & 31;
    const int quad = l >> 2;
    const int sub  = l & 3;
    const int dimg = (int)(64u * q) + w * 8 + quad;   // global hidden dim
    const int R    = sub * HHD + dimg;                // gate row

    const float* Whh = dir ? Whh_b : Whh_f;

    unsigned long long wr[64];
    const unsigned long long* wrow = (const unsigned long long*)(Whh + (size_t)R * HHD);
#pragma unroll
    for (int k = 0; k < 64; k++) wr[k] = wrow[k];

    if (tid < HHD) s_h[0][tid] = h0[dir * HHD + tid];
    float c = (sub == 0) ? c0[dir * HHD + dimg] : 0.0f;

    unsigned mbar_addr = smem_u32(&s_mbar);
    if (tid == 0) {
        asm volatile("mbarrier.init.shared.b64 [%0], 1;" :: "r"(mbar_addr) : "memory");
    }
    __syncthreads();
    asm volatile("barrier.cluster.arrive.aligned;" ::: "memory");
    asm volatile("barrier.cluster.wait.aligned;" ::: "memory");

    const float* pre = d_pre + (size_t)dir * TN * GG;
    float* hout = d_houtg + (size_t)dir * TN * HHD;

    const int b16  = l & 16;
    const int dim0 = (int)(64u * q) + w * 8 + (b16 >> 2);   // storing-lane base dim
    unsigned a_store0 = smem_u32(&s_h[0][dim0]);
    unsigned a_store1 = smem_u32(&s_h[1][dim0]);

    const float LOG2E   = 1.4426950408889634f;
    const float sc_mine = (sub == 2) ? 2.0f * LOG2E : -LOG2E;   // tanh(g) vs sigmoid

    float pv_cur = pre[(size_t)(dir ? (TN - 1) : 0) * GG + R];

    for (int s = 0; s < TN; s++) {
        const int cur = s & 1;
        const int t = dir ? (TN - 1 - s) : s;
        float pv = pv_cur;
        if (s + 1 < TN)
            pv_cur = pre[(size_t)(dir ? (TN - 2 - s) : (s + 1)) * GG + R];   // prefetch

        const ulonglong2* h2 = (const ulonglong2*)s_h[cur];
        unsigned long long aA = 0ull, aB = 0ull;

        // phase A: local half (written by our own stores last step)
        if (q == 0) { FMA_HALF(0, 0); } else { FMA_HALF(16, 32); }

        // phase B: wait for peer half (skipped at s=0; h0 preloaded)
        if (s) mbar_wait_parity_cluster(mbar_addr, (unsigned)((s - 1) & 1));

        // phase C: remote half
        if (q == 0) { FMA_HALF(16, 32); } else { FMA_HALF(0, 0); }

        float partial = (ull_lo(aA) + ull_hi(aA)) + (ull_lo(aB) + ull_hi(aB)) + pv;

        // unified per-lane nonlinearity: sigma = 1/(1+e^{-x}); tanh = 1-2/(1+e^{2x})
        float e = ex2f(sc_mine * partial);
        float dnm = rcpf(1.0f + e);
        float a = (sub == 2) ? fmaf(-2.0f, dnm, 1.0f) : dnm;

        // gather the 4 activations of this dim into the sub==0 lane
        int base = l & ~3;
        float ai = __shfl_sync(0xffffffffu, a, base);
        float af = __shfl_sync(0xffffffffu, a, base + 1);
        float ag = __shfl_sync(0xffffffffu, a, base + 2);
        float ao = __shfl_sync(0xffffffffu, a, base + 3);

        float hn = 0.0f;
        if (sub == 0) {
            c = fmaf(af, c, ai * ag);
            float e2 = ex2f(2.0f * LOG2E * c);
            float tc = fmaf(-2.0f, rcpf(1.0f + e2), 1.0f);
            hn = ao * tc;
        }

        // pack 4 hn values (quads b16/4 .. b16/4+3) into lanes 0 and 16
        float v0 = __shfl_sync(0xffffffffu, hn, b16);
        float v1 = __shfl_sync(0xffffffffu, hn, b16 + 4);
        float v2 = __shfl_sync(0xffffffffu, hn, b16 + 8);
        float v3 = __shfl_sync(0xffffffffu, hn, b16 + 12);

        if ((l & 15) == 0) {
            float4 vv = make_float4(v0, v1, v2, v3);
            *(float4*)&s_h[cur ^ 1][dim0] = vv;                       // local
            if (s + 1 < TN)
                st_remote_v4(cur ? a_store0 : a_store1, peer,
                             v0, v1, v2, v3);                         // peer
            *(float4*)&hout[(size_t)t * HHD + dim0] = vv;             // global
        }
        __syncthreads();   // orders local h writes CTA-wide (and remote sts before arrive)
        if (tid == 0 && s + 1 < TN) arrive_remote(mbar_addr, peer);
    }
    asm volatile("barrier.cluster.arrive.aligned;" ::: "memory");
    asm volatile("barrier.cluster.wait.aligned;" ::: "memory");
}

// ---------------- kernel 3: output projection ----------------
__global__ void feats_kernel(const float* __restrict__ W_out,
                             const float* __restrict__ b_out) {
    int t = blockIdx.x;
    int tid = threadIdx.x;   // 256
    __shared__ float s_hc[256];
    s_hc[tid] = (tid < HHD) ? d_houtg[(size_t)t * HHD + tid]
                            : d_houtg[(size_t)TN * HHD + (size_t)t * HHD + (tid - HHD)];
    __syncthreads();
    int w = tid >> 5, l = tid & 31;
    for (int k = w; k < KT; k += 8) {
        float acc = 0.0f;
#pragma unroll
        for (int jj = l; jj < 256; jj += 32) acc += W_out[k * 256 + jj] * s_hc[jj];
#pragma unroll
        for (int off = 16; off; off >>= 1) acc += __shfl_down_sync(0xffffffffu, acc, off);
        if (l == 0) d_feats[t * KT + k] = acc + b_out[k];
    }
}

// ---------------- kernel 4a: Viterbi forward (values only) ----------------
__global__ void viterbi_fwd_kernel(const float* __restrict__ transitions) {
    int lane = threadIdx.x;
    bool act = lane < KT;
    float tr[KT];
#pragma unroll
    for (int p = 0; p < KT; p++) {
        float v = NEGV;
        if (act) {
            v = transitions[lane * KT + p];
            if (lane == TSTART) v = NEGV;
            if (p == TSTOP)     v = NEGV;
        }
        tr[p] = v;
    }
    float trS = act ? ((lane == TSTOP) ? NEGV : transitions[TSTOP * KT + lane]) : NEGV;
    float fv = (lane == TSTART) ? 0.0f : NEGV;

    float f0 = act ? d_feats[0 * KT + lane] : 0.0f;
    float f1 = act ? d_feats[1 * KT + lane] : 0.0f;
    float f2 = act ? d_feats[2 * KT + lane] : 0.0f;

    for (int t = 0; t < TN; t++) {
        float fn = 0.0f;
        if (act && t + 3 < TN) fn = d_feats[(t + 3) * KT + lane];

        d_fvrow[t * 32 + lane] = fv;   // fv BEFORE step t (for bp recompute)

        float cc[24];
#pragma unroll
        for (int p = 0; p < KT; p++) cc[p] = __shfl_sync(0xffffffffu, fv, p) + tr[p];
        cc[23] = -3.0e38f;

        float a[12];
#pragma unroll
        for (int p = 0; p < 12; p++) a[p] = fmaxf(cc[2 * p], cc[2 * p + 1]);
        float b[6];
#pragma unroll
        for (int p = 0; p < 6; p++) b[p] = fmaxf(a[2 * p], a[2 * p + 1]);
        float c3[3];
#pragma unroll
        for (int p = 0; p < 3; p++) c3[p] = fmaxf(b[2 * p], b[2 * p + 1]);
        float best = fmaxf(fmaxf(c3[0], c3[1]), c3[2]);

        fv = best + f0;
        f0 = f1; f1 = f2; f2 = fn;
    }

    float term = act ? (fv + trS) : NEGV;
    int idx = lane;
#pragma unroll
    for (int off = 16; off; off >>= 1) {
        float ov = __shfl_down_sync(0xffffffffu, term, off);
        int   oi = __shfl_down_sync(0xffffffffu, idx,  off);
        if (ov > term || (ov == term && oi < idx)) { term = ov; idx = oi; }
    }
    __syncwarp();
    if (lane == 0) { d_score_g = term; d_last_tag = idx; }
}

// ---------------- kernel 4b: backpointer recompute (parallel over t) -------
__global__ void viterbi_bp_kernel(const float* __restrict__ transitions) {
    int wrp = threadIdx.x >> 5, lane = threadIdx.x & 31;
    int t = blockIdx.x * 8 + wrp;
    if (t >= TN) return;
    int k = lane;
    bool act = k < KT;

    float tr[KT];   // tr[p] = trans[k][p] constrained
#pragma unroll
    for (int p = 0; p < KT; p++) {
        float v = NEGV;
        if (act) {
            v = __ldg(&transitions[k * KT + p]);
            if (k == TSTART) v = NEGV;
            if (p == TSTOP)  v = NEGV;
        }
        tr[p] = v;
    }
    float fvv = d_fvrow[t * 32 + lane];

    float best = __shfl_sync(0xffffffffu, fvv, 0) + tr[0];
    int bp = 0;
#pragma unroll
    for (int p = 1; p < KT; p++) {
        float v = __shfl_sync(0xffffffffu, fvv, p) + tr[p];
        if (v > best) { best = v; bp = p; }   // first-argmax semantics
    }
    if (act) d_bp[t * KT + k] = (unsigned char)bp;
}

// ---------------- kernel 4c: backtrace over smem-staged bp table -----------
__global__ void viterbi_bt_kernel() {
    extern __shared__ unsigned char sbp[];   // TN * KT bytes
    int tid = threadIdx.x;
    const uint4* src = (const uint4*)d_bp;
    uint4* dst = (uint4*)sbp;
    for (int i = tid; i < (TN * KT) / 16; i += blockDim.x) dst[i] = src[i];
    __syncthreads();
    if (tid == 0) {
        int tag = d_last_tag;
        d_tags_g[TN - 1] = tag;
        for (int t = TN - 1; t > 0; t--) {
            tag = sbp[t * KT + tag];
            d_tags_g[t - 1] = tag;
        }
    }
}

// ---------------- kernel 5: write output ----------------
__global__ void epilogue_kernel(float* __restrict__ out, int n) {
    int i = blockIdx.x * blockDim.x + threadIdx.x;
    if (i >= n) return;
    float v;
    if (n == TN) {
        v = (float)d_tags_g[i];
    } else if (n == 1) {
        v = d_score_g;
    } else {
        v = (i == 0) ? d_score_g
                     : ((i - 1 < TN) ? (float)d_tags_g[i - 1] : 0.0f);
    }
    out[i] = v;
}

// ---------------- launch ----------------
extern "C" void kernel_launch(void* const* d_in, const int* in_sizes, int n_in,
                              void* d_out, int out_size) {
    const int*   sentence = (const int*)  d_in[0];
    const float* embed    = (const float*)d_in[1];
    const float* Wih_f    = (const float*)d_in[2];
    const float* Whh_f    = (const float*)d_in[3];
    const float* bih_f    = (const float*)d_in[4];
    const float* bhh_f    = (const float*)d_in[5];
    const float* Wih_b    = (const float*)d_in[6];
    const float* Whh_b    = (const float*)d_in[7];
    const float* bih_b    = (const float*)d_in[8];
    const float* bhh_b    = (const float*)d_in[9];
    const float* W_out    = (const float*)d_in[10];
    const float* b_out    = (const float*)d_in[11];
    const float* trans    = (const float*)d_in[12];
    const float* h0       = (const float*)d_in[13];
    const float* c0       = (const float*)d_in[14];

    pre_kernel<<<TN / 64, 512>>>(sentence, embed, Wih_f, bih_f, bhh_f,
                                 Wih_b, bih_b, bhh_b);                    // 1
    dummy_kernel<<<1, 32>>>();                                            // 2
    dummy_kernel<<<1, 32>>>();                                            // 3
    lstm_kernel<<<4, 256>>>(Whh_f, Whh_b, h0, c0);                        // 4 (ncu window)
    feats_kernel<<<TN, 256>>>(W_out, b_out);                              // 5
    viterbi_fwd_kernel<<<1, 32>>>(trans);                                 // 6
    viterbi_bp_kernel<<<TN / 8, 256>>>(trans);                            // 7

    int bt_smem = TN * KT + 64;
    cudaFuncSetAttribute(viterbi_bt_kernel,
                         cudaFuncAttributeMaxDynamicSharedMemorySize, bt_smem);
    viterbi_bt_kernel<<<1, 1024, bt_smem>>>();                            // 8

    int n = out_size;
    epilogue_kernel<<<(n + 255) / 256, 256>>>((float*)d_out, n);          // 9
}